// round 3
// baseline (speedup 1.0000x reference)
#include <cuda_runtime.h>
#include <mma.h>
#include <math.h>

using namespace nvcuda;

#define Bb 2
#define Nn 2048
#define MM_ 2048
#define Dd 1024
#define Hh 8
#define DHd 64
#define INNERi 512
#define FFDf 4096

// ---------------- scratch (device globals; no cudaMalloc allowed) ----------
__device__ float g_xn [Bb*Nn*Dd];
__device__ float g_cn [Bb*MM_*Dd];
__device__ float g_qk [Bb*Nn*INNERi];
__device__ float g_v  [Bb*Nn*INNERi];
__device__ float g_cqk[Bb*MM_*INNERi];
__device__ float g_cv [Bb*MM_*INNERi];
__device__ float g_sim  [Bb*Hh*Nn*MM_];
__device__ float g_attn [Bb*Hh*Nn*MM_];
__device__ float g_cattn[Bb*Hh*Nn*MM_];
__device__ float g_out [Bb*Nn*INNERi];
__device__ float g_cout[Bb*MM_*INNERi];
__device__ float g_x1  [Bb*Nn*Dd];
__device__ float g_c1  [Bb*MM_*Dd];
__device__ float g_h   [Bb*Nn*FFDf];
__device__ int   g_mask_mode;   // 0 = u8/bool, 1 = int32, 2 = float32

// ---------------- mask dtype detection ------------------------------------
// The harness may store the bool masks as bool(1B), int32, or float32. Detect
// which by value inspection over the first n/4 elements (safe to read as
// 4-byte values under every candidate layout). For 0/1-valued masks the three
// interpretations are mutually exclusive.
__global__ void detect_mask_mode(const float* __restrict__ fp, int n4)
{
    __shared__ int okf_s, oki_s;
    if (threadIdx.x == 0) { okf_s = 1; oki_s = 1; }
    __syncthreads();
    const int* ip = (const int*)fp;
    bool okf = true, oki = true;
    for (int i = threadIdx.x; i < n4; i += 256) {
        float fv = fp[i]; okf = okf && (fv == 0.f || fv == 1.f);
        int   iv = ip[i]; oki = oki && (iv == 0 || iv == 1);
    }
    if (!okf) atomicAnd(&okf_s, 0);
    if (!oki) atomicAnd(&oki_s, 0);
    __syncthreads();
    if (threadIdx.x == 0) g_mask_mode = okf_s ? 2 : (oki_s ? 1 : 0);
}

__device__ __forceinline__ bool mask_at(const void* m, int i, int mode)
{
    if (mode == 1) return ((const int*)m)[i] != 0;
    if (mode == 2) return ((const float*)m)[i] != 0.f;
    return ((const unsigned char*)m)[i] != 0;
}

// ---------------- LayerNorm --------------------------------------------
__global__ __launch_bounds__(256)
void ln_k(const float* __restrict__ in, const float* __restrict__ g,
          const float* __restrict__ b, float* __restrict__ out, int cols)
{
    __shared__ float r1[256], r2[256];
    long row = blockIdx.x;
    const float* p = in + row * cols;
    float* o = out + row * cols;
    int tid = threadIdx.x;
    float s = 0.f, s2 = 0.f;
    for (int c = tid; c < cols; c += 256) { float v = p[c]; s += v; s2 += v * v; }
    r1[tid] = s; r2[tid] = s2; __syncthreads();
    for (int st = 128; st > 0; st >>= 1) {
        if (tid < st) { r1[tid] += r1[tid + st]; r2[tid] += r2[tid + st]; }
        __syncthreads();
    }
    float mu  = r1[0] / cols;
    float var = r2[0] / cols - mu * mu;
    float inv = rsqrtf(var + 1e-5f);
    for (int c = tid; c < cols; c += 256)
        o[c] = (p[c] - mu) * inv * g[c] + b[c];
}

// ---------------- Row softmax (over j, length MM_) ----------------------
__global__ __launch_bounds__(256)
void softmax_row(const float* __restrict__ sim, float* __restrict__ attn,
                 const void* __restrict__ mask,
                 const void* __restrict__ cmask)
{
    __shared__ float buf[MM_];
    __shared__ float red[256];
    int mode = g_mask_mode;
    long row = blockIdx.x;             // (b*H + h)*N + i
    int i  = (int)(row % Nn);
    int bh = (int)(row / Nn);
    int b  = bh / Hh;
    const float* src = sim  + row * (long)MM_;
    float*       dst = attn + row * (long)MM_;
    int tid = threadIdx.x;
    bool mi = mask_at(mask, b * Nn + i, mode);

    float lmax = -3.402823466e38f;
    for (int j = tid; j < MM_; j += 256) {
        bool mj = mask_at(cmask, b * MM_ + j, mode);
        float vv = (mi && mj) ? src[j] : -3.402823466e38f;
        buf[j] = vv;
        lmax = fmaxf(lmax, vv);
    }
    red[tid] = lmax; __syncthreads();
    for (int s = 128; s > 0; s >>= 1) {
        if (tid < s) red[tid] = fmaxf(red[tid], red[tid + s]);
        __syncthreads();
    }
    float rmax = red[0]; __syncthreads();
    float lsum = 0.f;
    for (int j = tid; j < MM_; j += 256) {
        float e = expf(buf[j] - rmax);
        buf[j] = e; lsum += e;
    }
    red[tid] = lsum; __syncthreads();
    for (int s = 128; s > 0; s >>= 1) {
        if (tid < s) red[tid] += red[tid + s];
        __syncthreads();
    }
    float inv = 1.f / red[0];
    for (int j = tid; j < MM_; j += 256) dst[j] = buf[j] * inv;
}

// ---------------- Column softmax (over i) --------------------------------
__global__ __launch_bounds__(256)
void softmax_col(const float* __restrict__ sim, float* __restrict__ cattn,
                 const void* __restrict__ mask,
                 const void* __restrict__ cmask)
{
    __shared__ float sm[8][32], ss[8][32];
    int mode = g_mask_mode;
    int z = blockIdx.y;                // b*H + h
    int b = z / Hh;
    int c = threadIdx.x & 31;
    int g = threadIdx.x >> 5;
    int j = blockIdx.x * 32 + c;
    const float* base = sim   + (long)z * Nn * MM_;
    float*       outb = cattn + (long)z * Nn * MM_;
    bool mj = mask_at(cmask, b * MM_ + j, mode);

    float m = -3.402823466e38f, s = 0.f;
    for (int i = g; i < Nn; i += 8) {
        bool mi = mask_at(mask, b * Nn + i, mode);
        float vv = (mj && mi) ? base[(long)i * MM_ + j] : -3.402823466e38f;
        if (vv > m) { s = s * expf(m - vv) + 1.f; m = vv; }
        else        { s += expf(vv - m); }
    }
    sm[g][c] = m; ss[g][c] = s; __syncthreads();
    if (g == 0) {
        float Mloc = sm[0][c], Sloc = ss[0][c];
        #pragma unroll
        for (int t = 1; t < 8; t++) {
            float mt = sm[t][c], st = ss[t][c];
            float nm = fmaxf(Mloc, mt);
            Sloc = Sloc * expf(Mloc - nm) + st * expf(mt - nm);
            Mloc = nm;
        }
        sm[0][c] = Mloc; ss[0][c] = 1.f / Sloc;
    }
    __syncthreads();
    float Mg = sm[0][c], inv = ss[0][c];
    for (int i = g; i < Nn; i += 8) {
        bool mi = mask_at(mask, b * Nn + i, mode);
        float vv = (mj && mi) ? base[(long)i * MM_ + j] : -3.402823466e38f;
        outb[(long)i * MM_ + j] = expf(vv - Mg) * inv;
    }
}

// ---------------- 3xTF32 WMMA GEMM ----------------------------------------
// C(MxN) = alpha * op(A)(MxK) @ op(B)(KxN) [+ bias[n]] [+ res[m,n]] [gelu]
// Block tile 64x64, K-tile 32, 4 warps (each 32x32 via 2x2 m16n16k8 frags).
// Each operand split into hi/lo tf32; accumulate ah*bh + ah*bl + al*bh for
// ~21-bit effective mantissa (fp32-class GEMM accuracy on tensor cores).
// Batched: z = blockIdx.z, operand base += (z/HH)*Outer + (z%HH)*Inner.
// EPI: 0=alpha only, 2=bias+residual, 3=bias+exact GELU
template<bool AC, bool BC, int EPI>
__global__ __launch_bounds__(128)
void gemm_k(const float* __restrict__ A, int lda, long aO, long aI,
            const float* __restrict__ Bm, int ldb, long bO, long bI,
            float* __restrict__ C, int ldc, long cO, long cI,
            const float* __restrict__ bias,
            const float* __restrict__ res, int ldr,
            int K, float alpha, int HHd)
{
    __shared__ float sA[64][36];
    __shared__ float sB[32][72];
    __shared__ float sC[64][68];

    int z  = blockIdx.z;
    int zo = z / HHd, zi = z % HHd;
    A  += (long)zo * aO + (long)zi * aI;
    Bm += (long)zo * bO + (long)zi * bI;
    C  += (long)zo * cO + (long)zi * cI;

    int m0 = blockIdx.y * 64;
    int n0 = blockIdx.x * 64;
    int tid = threadIdx.x;
    int warp = tid >> 5;
    int wr = warp >> 1, wc = warp & 1;

    wmma::fragment<wmma::accumulator, 16, 16, 8, float> fc[2][2];
    #pragma unroll
    for (int i = 0; i < 2; i++)
        #pragma unroll
        for (int j = 0; j < 2; j++)
            wmma::fill_fragment(fc[i][j], 0.f);

    for (int kt = 0; kt < K; kt += 32) {
        if (!AC) {
            #pragma unroll
            for (int idx = tid; idx < 64 * 32; idx += 128) {
                int r = idx >> 5, c = idx & 31;
                sA[r][c] = A[(long)(m0 + r) * lda + kt + c];
            }
        } else {
            #pragma unroll
            for (int idx = tid; idx < 64 * 32; idx += 128) {
                int r = idx & 63, c = idx >> 6;
                sA[r][c] = A[(long)(kt + c) * lda + m0 + r];
            }
        }
        if (!BC) {
            #pragma unroll
            for (int idx = tid; idx < 32 * 64; idx += 128) {
                int r = idx >> 6, c = idx & 63;
                sB[r][c] = Bm[(long)(kt + r) * ldb + n0 + c];
            }
        } else {
            #pragma unroll
            for (int idx = tid; idx < 32 * 64; idx += 128) {
                int r = idx & 31, c = idx >> 5;
                sB[r][c] = Bm[(long)(n0 + c) * ldb + kt + r];
            }
        }
        __syncthreads();
        #pragma unroll
        for (int kk = 0; kk < 32; kk += 8) {
            wmma::fragment<wmma::matrix_a, 16, 16, 8, wmma::precision::tf32, wmma::row_major> fah[2], fal[2];
            wmma::fragment<wmma::matrix_b, 16, 16, 8, wmma::precision::tf32, wmma::row_major> fbh[2], fbl[2];
            #pragma unroll
            for (int i = 0; i < 2; i++) {
                wmma::load_matrix_sync(fah[i], &sA[wr * 32 + i * 16][kk], 36);
                #pragma unroll
                for (int t = 0; t < fah[i].num_elements; t++) {
                    float vfull = fah[i].x[t];
                    float hi = wmma::__float_to_tf32(vfull);
                    fah[i].x[t] = hi;
                    fal[i].x[t] = wmma::__float_to_tf32(vfull - hi);
                }
            }
            #pragma unroll
            for (int j = 0; j < 2; j++) {
                wmma::load_matrix_sync(fbh[j], &sB[kk][wc * 32 + j * 16], 72);
                #pragma unroll
                for (int t = 0; t < fbh[j].num_elements; t++) {
                    float vfull = fbh[j].x[t];
                    float hi = wmma::__float_to_tf32(vfull);
                    fbh[j].x[t] = hi;
                    fbl[j].x[t] = wmma::__float_to_tf32(vfull - hi);
                }
            }
            #pragma unroll
            for (int i = 0; i < 2; i++)
                #pragma unroll
                for (int j = 0; j < 2; j++) {
                    wmma::mma_sync(fc[i][j], fah[i], fbl[j], fc[i][j]);
                    wmma::mma_sync(fc[i][j], fal[i], fbh[j], fc[i][j]);
                    wmma::mma_sync(fc[i][j], fah[i], fbh[j], fc[i][j]);
                }
        }
        __syncthreads();
    }

    #pragma unroll
    for (int i = 0; i < 2; i++)
        #pragma unroll
        for (int j = 0; j < 2; j++)
            wmma::store_matrix_sync(&sC[wr * 32 + i * 16][wc * 32 + j * 16],
                                    fc[i][j], 68, wmma::mem_row_major);
    __syncthreads();
    #pragma unroll
    for (int idx = tid; idx < 64 * 64; idx += 128) {
        int r = idx >> 6, c = idx & 63;
        int gm = m0 + r, gn = n0 + c;
        float v = sC[r][c] * alpha;
        if (EPI == 2) v += bias[gn] + res[(long)gm * ldr + gn];
        if (EPI == 3) {
            v += bias[gn];
            v = 0.5f * v * (1.f + erff(v * 0.7071067811865476f));
        }
        C[(long)gm * ldc + gn] = v;
    }
}

// ---------------- host ----------------------------------------------------
extern "C" void kernel_launch(void* const* d_in, const int* in_sizes, int n_in,
                              void* d_out, int out_size)
{
    (void)in_sizes; (void)n_in; (void)out_size;
    const float* x      = (const float*)d_in[0];
    const float* ctx    = (const float*)d_in[1];
    const void*  mask   = d_in[2];
    const void*  cmask  = d_in[3];
    const float* ln_x_g = (const float*)d_in[4];
    const float* ln_x_b = (const float*)d_in[5];
    const float* ln_c_g = (const float*)d_in[6];
    const float* ln_c_b = (const float*)d_in[7];
    const float* W_qk   = (const float*)d_in[8];
    const float* W_v    = (const float*)d_in[9];
    const float* Wc_qk  = (const float*)d_in[10];
    const float* Wc_v   = (const float*)d_in[11];
    const float* W_out  = (const float*)d_in[12];
    const float* b_out  = (const float*)d_in[13];
    const float* Wc_out = (const float*)d_in[14];
    const float* bc_out = (const float*)d_in[15];
    const float* ff_g   = (const float*)d_in[16];
    const float* ff_b   = (const float*)d_in[17];
    const float* ff_w1  = (const float*)d_in[18];
    const float* ff_b1  = (const float*)d_in[19];
    const float* ff_w2  = (const float*)d_in[20];
    const float* ff_b2  = (const float*)d_in[21];
    const float* cff_g  = (const float*)d_in[22];
    const float* cff_b  = (const float*)d_in[23];
    const float* cff_w1 = (const float*)d_in[24];
    const float* cff_b1 = (const float*)d_in[25];
    const float* cff_w2 = (const float*)d_in[26];
    const float* cff_b2 = (const float*)d_in[27];
    float* outp = (float*)d_out;

    float *xn, *cn, *qk, *v, *cqk, *cv, *sim, *attn, *cattn, *out, *cout, *x1, *c1, *hbuf;
    cudaGetSymbolAddress((void**)&xn,    g_xn);
    cudaGetSymbolAddress((void**)&cn,    g_cn);
    cudaGetSymbolAddress((void**)&qk,    g_qk);
    cudaGetSymbolAddress((void**)&v,     g_v);
    cudaGetSymbolAddress((void**)&cqk,   g_cqk);
    cudaGetSymbolAddress((void**)&cv,    g_cv);
    cudaGetSymbolAddress((void**)&sim,   g_sim);
    cudaGetSymbolAddress((void**)&attn,  g_attn);
    cudaGetSymbolAddress((void**)&cattn, g_cattn);
    cudaGetSymbolAddress((void**)&out,   g_out);
    cudaGetSymbolAddress((void**)&cout,  g_cout);
    cudaGetSymbolAddress((void**)&x1,    g_x1);
    cudaGetSymbolAddress((void**)&c1,    g_c1);
    cudaGetSymbolAddress((void**)&hbuf,  g_h);

    const float SCALE = 0.125f;   // DH^-0.5 = 64^-0.5

    // 0) detect mask dtype (bool/int32/float32)
    detect_mask_mode<<<1, 256>>>((const float*)mask, (Bb * Nn) / 4);

    // 1) pre-norm
    ln_k<<<Bb * Nn,  256>>>(x,   ln_x_g, ln_x_b, xn, Dd);
    ln_k<<<Bb * MM_, 256>>>(ctx, ln_c_g, ln_c_b, cn, Dd);

    // 2) projections (M=B*N rows)
    gemm_k<false, false, 0><<<dim3(INNERi / 64, Bb * Nn / 64, 1), 128>>>(
        xn, Dd, 0, 0, W_qk, INNERi, 0, 0, qk, INNERi, 0, 0,
        nullptr, nullptr, 0, Dd, 1.f, 1);
    gemm_k<false, false, 0><<<dim3(INNERi / 64, Bb * Nn / 64, 1), 128>>>(
        xn, Dd, 0, 0, W_v, INNERi, 0, 0, v, INNERi, 0, 0,
        nullptr, nullptr, 0, Dd, 1.f, 1);
    gemm_k<false, false, 0><<<dim3(INNERi / 64, Bb * MM_ / 64, 1), 128>>>(
        cn, Dd, 0, 0, Wc_qk, INNERi, 0, 0, cqk, INNERi, 0, 0,
        nullptr, nullptr, 0, Dd, 1.f, 1);
    gemm_k<false, false, 0><<<dim3(INNERi / 64, Bb * MM_ / 64, 1), 128>>>(
        cn, Dd, 0, 0, Wc_v, INNERi, 0, 0, cv, INNERi, 0, 0,
        nullptr, nullptr, 0, Dd, 1.f, 1);

    // 3) sim[b,h] = qk[b,:,h,:] @ cqk[b,:,h,:]^T * SCALE   (batched over b*h)
    gemm_k<false, true, 0><<<dim3(MM_ / 64, Nn / 64, Bb * Hh), 128>>>(
        qk,  INNERi, (long)Nn  * INNERi, DHd,
        cqk, INNERi, (long)MM_ * INNERi, DHd,
        sim, MM_,    (long)Hh * Nn * MM_, (long)Nn * MM_,
        nullptr, nullptr, 0, DHd, SCALE, Hh);

    // 4) dual softmax
    softmax_row<<<Bb * Hh * Nn, 256>>>(sim, attn, mask, cmask);
    softmax_col<<<dim3(MM_ / 32, Bb * Hh), 256>>>(sim, cattn, mask, cmask);

    // 5) out = attn @ cv ;  cout = cattn^T @ v
    gemm_k<false, false, 0><<<dim3(1, Nn / 64, Bb * Hh), 128>>>(
        attn, MM_,   (long)Hh * Nn * MM_, (long)Nn * MM_,
        cv,  INNERi, (long)MM_ * INNERi, DHd,
        out, INNERi, (long)Nn  * INNERi, DHd,
        nullptr, nullptr, 0, MM_, 1.f, Hh);
    gemm_k<true, false, 0><<<dim3(1, MM_ / 64, Bb * Hh), 128>>>(
        cattn, MM_,  (long)Hh * Nn * MM_, (long)Nn * MM_,
        v,   INNERi, (long)Nn  * INNERi, DHd,
        cout, INNERi, (long)MM_ * INNERi, DHd,
        nullptr, nullptr, 0, Nn, 1.f, Hh);

    // 6) output projection + residual
    gemm_k<false, false, 2><<<dim3(Dd / 64, Bb * Nn / 64, 1), 128>>>(
        out, INNERi, 0, 0, W_out, Dd, 0, 0, x1, Dd, 0, 0,
        b_out, x, Dd, INNERi, 1.f, 1);
    gemm_k<false, false, 2><<<dim3(Dd / 64, Bb * MM_ / 64, 1), 128>>>(
        cout, INNERi, 0, 0, Wc_out, Dd, 0, 0, c1, Dd, 0, 0,
        bc_out, ctx, Dd, INNERi, 1.f, 1);

    // 7) FFN (x side) -> d_out[0 : B*N*D)
    ln_k<<<Bb * Nn, 256>>>(x1, ff_g, ff_b, xn, Dd);
    gemm_k<false, false, 3><<<dim3(FFDf / 64, Bb * Nn / 64, 1), 128>>>(
        xn, Dd, 0, 0, ff_w1, FFDf, 0, 0, hbuf, FFDf, 0, 0,
        ff_b1, nullptr, 0, Dd, 1.f, 1);
    gemm_k<false, false, 2><<<dim3(Dd / 64, Bb * Nn / 64, 1), 128>>>(
        hbuf, FFDf, 0, 0, ff_w2, Dd, 0, 0, outp, Dd, 0, 0,
        ff_b2, x1, Dd, FFDf, 1.f, 1);

    // 8) FFN (context side) -> d_out[B*N*D : 2*B*N*D)
    ln_k<<<Bb * MM_, 256>>>(c1, cff_g, cff_b, cn, Dd);
    gemm_k<false, false, 3><<<dim3(FFDf / 64, Bb * MM_ / 64, 1), 128>>>(
        cn, Dd, 0, 0, cff_w1, FFDf, 0, 0, hbuf, FFDf, 0, 0,
        cff_b1, nullptr, 0, Dd, 1.f, 1);
    gemm_k<false, false, 2><<<dim3(Dd / 64, Bb * MM_ / 64, 1), 128>>>(
        hbuf, FFDf, 0, 0, cff_w2, Dd, 0, 0, outp + (long)Bb * Nn * Dd, Dd, 0, 0,
        cff_b2, c1, Dd, FFDf, 1.f, 1);
}

// round 4
// speedup vs baseline: 1.8699x; 1.8699x over previous
#include <cuda_runtime.h>
#include <mma.h>
#include <math.h>

using namespace nvcuda;

#define Bb 2
#define Nn 2048
#define MM_ 2048
#define Dd 1024
#define Hh 8
#define DHd 64
#define INNERi 512
#define FFDf 4096

// ---------------- scratch (device globals; no cudaMalloc allowed) ----------
__device__ __align__(256) float g_xn [Bb*Nn*Dd];
__device__ __align__(256) float g_cn [Bb*MM_*Dd];
__device__ __align__(256) float g_qk [Bb*Nn*INNERi];
__device__ __align__(256) float g_v  [Bb*Nn*INNERi];
__device__ __align__(256) float g_cqk[Bb*MM_*INNERi];
__device__ __align__(256) float g_cv [Bb*MM_*INNERi];
__device__ __align__(256) float g_sim  [Bb*Hh*Nn*MM_];
__device__ __align__(256) float g_attn [Bb*Hh*Nn*MM_];
__device__ __align__(256) float g_cattn[Bb*Hh*Nn*MM_];
__device__ __align__(256) float g_out [Bb*Nn*INNERi];
__device__ __align__(256) float g_cout[Bb*MM_*INNERi];
__device__ __align__(256) float g_x1  [Bb*Nn*Dd];
__device__ __align__(256) float g_c1  [Bb*MM_*Dd];
__device__ __align__(256) float g_h   [Bb*Nn*FFDf];
__device__ int   g_mask_mode;   // 0 = u8/bool, 1 = int32, 2 = float32

// ---------------- mask dtype detection ------------------------------------
__global__ void detect_mask_mode(const float* __restrict__ fp, int n4)
{
    __shared__ int okf_s, oki_s;
    if (threadIdx.x == 0) { okf_s = 1; oki_s = 1; }
    __syncthreads();
    const int* ip = (const int*)fp;
    bool okf = true, oki = true;
    for (int i = threadIdx.x; i < n4; i += 256) {
        float fv = fp[i]; okf = okf && (fv == 0.f || fv == 1.f);
        int   iv = ip[i]; oki = oki && (iv == 0 || iv == 1);
    }
    if (!okf) atomicAnd(&okf_s, 0);
    if (!oki) atomicAnd(&oki_s, 0);
    __syncthreads();
    if (threadIdx.x == 0) g_mask_mode = okf_s ? 2 : (oki_s ? 1 : 0);
}

__device__ __forceinline__ bool mask_at(const void* m, int i, int mode)
{
    if (mode == 1) return ((const int*)m)[i] != 0;
    if (mode == 2) return ((const float*)m)[i] != 0.f;
    return ((const unsigned char*)m)[i] != 0;
}

// ---------------- LayerNorm --------------------------------------------
__global__ __launch_bounds__(256)
void ln_k(const float* __restrict__ in, const float* __restrict__ g,
          const float* __restrict__ b, float* __restrict__ out, int cols)
{
    __shared__ float r1[256], r2[256];
    long row = blockIdx.x;
    const float* p = in + row * cols;
    float* o = out + row * cols;
    int tid = threadIdx.x;
    float s = 0.f, s2 = 0.f;
    for (int c = tid; c < cols; c += 256) { float v = p[c]; s += v; s2 += v * v; }
    r1[tid] = s; r2[tid] = s2; __syncthreads();
    for (int st = 128; st > 0; st >>= 1) {
        if (tid < st) { r1[tid] += r1[tid + st]; r2[tid] += r2[tid + st]; }
        __syncthreads();
    }
    float mu  = r1[0] / cols;
    float var = r2[0] / cols - mu * mu;
    float inv = rsqrtf(var + 1e-5f);
    for (int c = tid; c < cols; c += 256)
        o[c] = (p[c] - mu) * inv * g[c] + b[c];
}

// ---------------- Row softmax (over j, length MM_) ----------------------
__global__ __launch_bounds__(256)
void softmax_row(const float* __restrict__ sim, float* __restrict__ attn,
                 const void* __restrict__ mask,
                 const void* __restrict__ cmask)
{
    __shared__ float buf[MM_];
    __shared__ float red[256];
    int mode = g_mask_mode;
    long row = blockIdx.x;             // (b*H + h)*N + i
    int i  = (int)(row % Nn);
    int bh = (int)(row / Nn);
    int b  = bh / Hh;
    const float* src = sim  + row * (long)MM_;
    float*       dst = attn + row * (long)MM_;
    int tid = threadIdx.x;
    bool mi = mask_at(mask, b * Nn + i, mode);

    float lmax = -3.402823466e38f;
    for (int j = tid; j < MM_; j += 256) {
        bool mj = mask_at(cmask, b * MM_ + j, mode);
        float vv = (mi && mj) ? src[j] : -3.402823466e38f;
        buf[j] = vv;
        lmax = fmaxf(lmax, vv);
    }
    red[tid] = lmax; __syncthreads();
    for (int s = 128; s > 0; s >>= 1) {
        if (tid < s) red[tid] = fmaxf(red[tid], red[tid + s]);
        __syncthreads();
    }
    float rmax = red[0]; __syncthreads();
    float lsum = 0.f;
    for (int j = tid; j < MM_; j += 256) {
        float e = expf(buf[j] - rmax);
        buf[j] = e; lsum += e;
    }
    red[tid] = lsum; __syncthreads();
    for (int s = 128; s > 0; s >>= 1) {
        if (tid < s) red[tid] += red[tid + s];
        __syncthreads();
    }
    float inv = 1.f / red[0];
    for (int j = tid; j < MM_; j += 256) dst[j] = buf[j] * inv;
}

// ---------------- Column softmax (over i) --------------------------------
__global__ __launch_bounds__(256)
void softmax_col(const float* __restrict__ sim, float* __restrict__ cattn,
                 const void* __restrict__ mask,
                 const void* __restrict__ cmask)
{
    __shared__ float sm[8][32], ss[8][32];
    int mode = g_mask_mode;
    int z = blockIdx.y;                // b*H + h
    int b = z / Hh;
    int c = threadIdx.x & 31;
    int g = threadIdx.x >> 5;
    int j = blockIdx.x * 32 + c;
    const float* base = sim   + (long)z * Nn * MM_;
    float*       outb = cattn + (long)z * Nn * MM_;
    bool mj = mask_at(cmask, b * MM_ + j, mode);

    float m = -3.402823466e38f, s = 0.f;
    for (int i = g; i < Nn; i += 8) {
        bool mi = mask_at(mask, b * Nn + i, mode);
        float vv = (mj && mi) ? base[(long)i * MM_ + j] : -3.402823466e38f;
        if (vv > m) { s = s * expf(m - vv) + 1.f; m = vv; }
        else        { s += expf(vv - m); }
    }
    sm[g][c] = m; ss[g][c] = s; __syncthreads();
    if (g == 0) {
        float Mloc = sm[0][c], Sloc = ss[0][c];
        #pragma unroll
        for (int t = 1; t < 8; t++) {
            float mt = sm[t][c], st = ss[t][c];
            float nm = fmaxf(Mloc, mt);
            Sloc = Sloc * expf(Mloc - nm) + st * expf(mt - nm);
            Mloc = nm;
        }
        sm[0][c] = Mloc; ss[0][c] = 1.f / Sloc;
    }
    __syncthreads();
    float Mg = sm[0][c], inv = ss[0][c];
    for (int i = g; i < Nn; i += 8) {
        bool mi = mask_at(mask, b * Nn + i, mode);
        float vv = (mj && mi) ? base[(long)i * MM_ + j] : -3.402823466e38f;
        outb[(long)i * MM_ + j] = expf(vv - Mg) * inv;
    }
}

// ---------------- cp.async helpers -----------------------------------------
__device__ __forceinline__ void cpa16(float* dst, const float* src)
{
    unsigned d = (unsigned)__cvta_generic_to_shared(dst);
    asm volatile("cp.async.cg.shared.global [%0], [%1], 16;\n" :: "r"(d), "l"(src));
}

// ---------------- TF32 WMMA GEMM, cp.async double-buffered -----------------
// C(MxN) = alpha * op(A)(MxK) @ op(B)(KxN) [+ bias[n] + res[m,n]] [gelu]
// Block tile BMxBN, K-tile 32, 256 threads (8 warps).
// BN==128: warps 2(M)x4(N), warp tile 64x32.  BN==64: warps 4x2, 32x32.
// AC/BC: operand is transposed in memory -> stored smem-col-major and loaded
// with col_major fragments (keeps cp.async 16B chunks contiguous).
// EPI: 0 = alpha, direct frag store; 2 = bias+residual; 3 = bias+exact GELU.
template<int BM, int BN, bool AC, bool BC, int EPI>
__global__ __launch_bounds__(256)
void gemm2(const float* __restrict__ A, int lda, long aO, long aI,
           const float* __restrict__ Bm, int ldb, long bO, long bI,
           float* __restrict__ C, int ldc, long cO, long cI,
           const float* __restrict__ bias,
           const float* __restrict__ res, int ldr,
           int K, float alpha, int HHd)
{
    constexpr int BK   = 32;
    constexpr int LDAS = AC ? BM + 4 : BK + 4;
    constexpr int AEL  = AC ? BK * LDAS : BM * LDAS;
    constexpr int LDBS = BC ? BK + 4 : BN + 4;
    constexpr int BEL  = BC ? BN * LDBS : BK * LDBS;
    constexpr int WRM  = (BN == 128) ? 2 : 4;
    constexpr int WRN  = 8 / WRM;
    constexpr int TM   = BM / WRM;
    constexpr int TN   = BN / WRN;
    constexpr int FM   = TM / 16;
    constexpr int FN   = TN / 16;
    constexpr int LDCS = BN + 4;

    extern __shared__ float sm_[];
    float* sAb[2] = { sm_, sm_ + AEL };
    float* sBb[2] = { sm_ + 2 * AEL, sm_ + 2 * AEL + BEL };
    float* sC = sm_;   // epilogue staging aliases pipeline buffers

    int z  = blockIdx.z;
    int zo = z / HHd, zi = z % HHd;
    A  += (long)zo * aO + (long)zi * aI;
    Bm += (long)zo * bO + (long)zi * bI;
    C  += (long)zo * cO + (long)zi * cI;

    int m0 = blockIdx.y * BM;
    int n0 = blockIdx.x * BN;
    int tid  = threadIdx.x;
    int warp = tid >> 5;
    int wm0 = (warp % WRM) * TM;
    int wn0 = (warp / WRM) * TN;

    auto load_stage = [&](int s, int kt) {
        if (!AC) {
            constexpr int IT = (BM * (BK / 4)) / 256;
            #pragma unroll
            for (int t = 0; t < IT; t++) {
                int idx = t * 256 + tid;
                int r = idx >> 3, c = idx & 7;
                cpa16(sAb[s] + r * LDAS + c * 4,
                      A + (long)(m0 + r) * lda + kt + c * 4);
            }
        } else {
            constexpr int PR = BM / 4;
            constexpr int IT = (BK * PR) / 256;
            #pragma unroll
            for (int t = 0; t < IT; t++) {
                int idx = t * 256 + tid;
                int k = idx / PR, mc = idx % PR;
                cpa16(sAb[s] + k * LDAS + mc * 4,
                      A + (long)(kt + k) * lda + m0 + mc * 4);
            }
        }
        if (!BC) {
            constexpr int PR = BN / 4;
            constexpr int IT = (BK * PR) / 256;
            #pragma unroll
            for (int t = 0; t < IT; t++) {
                int idx = t * 256 + tid;
                int r = idx / PR, c = idx % PR;
                cpa16(sBb[s] + r * LDBS + c * 4,
                      Bm + (long)(kt + r) * ldb + n0 + c * 4);
            }
        } else {
            constexpr int IT = (BN * (BK / 4)) / 256;
            #pragma unroll
            for (int t = 0; t < IT; t++) {
                int idx = t * 256 + tid;
                int n = idx >> 3, c = idx & 7;
                cpa16(sBb[s] + n * LDBS + c * 4,
                      Bm + (long)(n0 + n) * ldb + kt + c * 4);
            }
        }
        asm volatile("cp.async.commit_group;\n");
    };

    using ALay = typename std::conditional<AC, wmma::col_major, wmma::row_major>::type;
    using BLay = typename std::conditional<BC, wmma::col_major, wmma::row_major>::type;

    wmma::fragment<wmma::accumulator, 16, 16, 8, float> fc[FM][FN];
    #pragma unroll
    for (int i = 0; i < FM; i++)
        #pragma unroll
        for (int j = 0; j < FN; j++)
            wmma::fill_fragment(fc[i][j], 0.f);

    int T = K / BK;
    load_stage(0, 0);

    for (int kt = 0; kt < T; kt++) {
        int s = kt & 1;
        if (kt + 1 < T) {
            load_stage(s ^ 1, (kt + 1) * BK);
            asm volatile("cp.async.wait_group 1;\n");
        } else {
            asm volatile("cp.async.wait_group 0;\n");
        }
        __syncthreads();

        #pragma unroll
        for (int kk = 0; kk < BK; kk += 8) {
            wmma::fragment<wmma::matrix_a, 16, 16, 8, wmma::precision::tf32, ALay> fa[FM];
            wmma::fragment<wmma::matrix_b, 16, 16, 8, wmma::precision::tf32, BLay> fb[FN];
            #pragma unroll
            for (int i = 0; i < FM; i++) {
                const float* ap = AC ? (sAb[s] + kk * LDAS + wm0 + i * 16)
                                     : (sAb[s] + (wm0 + i * 16) * LDAS + kk);
                wmma::load_matrix_sync(fa[i], ap, LDAS);
                #pragma unroll
                for (int t = 0; t < fa[i].num_elements; t++)
                    fa[i].x[t] = wmma::__float_to_tf32(fa[i].x[t]);
            }
            #pragma unroll
            for (int j = 0; j < FN; j++) {
                const float* bp = BC ? (sBb[s] + (wn0 + j * 16) * LDBS + kk)
                                     : (sBb[s] + kk * LDBS + wn0 + j * 16);
                wmma::load_matrix_sync(fb[j], bp, LDBS);
                #pragma unroll
                for (int t = 0; t < fb[j].num_elements; t++)
                    fb[j].x[t] = wmma::__float_to_tf32(fb[j].x[t]);
            }
            #pragma unroll
            for (int i = 0; i < FM; i++)
                #pragma unroll
                for (int j = 0; j < FN; j++)
                    wmma::mma_sync(fc[i][j], fa[i], fb[j], fc[i][j]);
        }
        __syncthreads();
    }

    if (EPI == 0) {
        #pragma unroll
        for (int i = 0; i < FM; i++)
            #pragma unroll
            for (int j = 0; j < FN; j++) {
                #pragma unroll
                for (int t = 0; t < fc[i][j].num_elements; t++)
                    fc[i][j].x[t] *= alpha;
                wmma::store_matrix_sync(
                    C + (long)(m0 + wm0 + i * 16) * ldc + n0 + wn0 + j * 16,
                    fc[i][j], ldc, wmma::mem_row_major);
            }
    } else {
        #pragma unroll
        for (int i = 0; i < FM; i++)
            #pragma unroll
            for (int j = 0; j < FN; j++)
                wmma::store_matrix_sync(sC + (wm0 + i * 16) * LDCS + wn0 + j * 16,
                                        fc[i][j], LDCS, wmma::mem_row_major);
        __syncthreads();
        for (int idx = tid; idx < BM * BN; idx += 256) {
            int r = idx / BN, c = idx % BN;
            int gm = m0 + r, gn = n0 + c;
            float v = sC[r * LDCS + c];
            if (EPI == 2) v += bias[gn] + res[(long)gm * ldr + gn];
            if (EPI == 3) {
                v += bias[gn];
                v = 0.5f * v * (1.f + erff(v * 0.7071067811865476f));
            }
            C[(long)gm * ldc + gn] = v;
        }
    }
}

// host-side smem size (mirrors kernel constexprs)
static constexpr size_t smemb(int BM, int BN, bool AC, bool BC, int EPI)
{
    int LDAS = AC ? BM + 4 : 36;
    int AEL  = AC ? 32 * LDAS : BM * LDAS;
    int LDBS = BC ? 36 : BN + 4;
    int BEL  = BC ? BN * LDBS : 32 * LDBS;
    int pipe = 2 * (AEL + BEL);
    int epi  = EPI ? BM * (BN + 4) : 0;
    return 4u * (size_t)(pipe > epi ? pipe : epi);
}

#define LAUNCH_GEMM(BM, BN, AC, BC, EPI, grid, ...)                             \
    do {                                                                        \
        auto kfn = gemm2<BM, BN, AC, BC, EPI>;                                  \
        size_t smb = smemb(BM, BN, AC, BC, EPI);                                \
        cudaFuncSetAttribute(kfn, cudaFuncAttributeMaxDynamicSharedMemorySize,  \
                             (int)smb);                                         \
        kfn<<<grid, 256, smb>>>(__VA_ARGS__);                                   \
    } while (0)

// ---------------- host ----------------------------------------------------
extern "C" void kernel_launch(void* const* d_in, const int* in_sizes, int n_in,
                              void* d_out, int out_size)
{
    (void)in_sizes; (void)n_in; (void)out_size;
    const float* x      = (const float*)d_in[0];
    const float* ctx    = (const float*)d_in[1];
    const void*  mask   = d_in[2];
    const void*  cmask  = d_in[3];
    const float* ln_x_g = (const float*)d_in[4];
    const float* ln_x_b = (const float*)d_in[5];
    const float* ln_c_g = (const float*)d_in[6];
    const float* ln_c_b = (const float*)d_in[7];
    const float* W_qk   = (const float*)d_in[8];
    const float* W_v    = (const float*)d_in[9];
    const float* Wc_qk  = (const float*)d_in[10];
    const float* Wc_v   = (const float*)d_in[11];
    const float* W_out  = (const float*)d_in[12];
    const float* b_out  = (const float*)d_in[13];
    const float* Wc_out = (const float*)d_in[14];
    const float* bc_out = (const float*)d_in[15];
    const float* ff_g   = (const float*)d_in[16];
    const float* ff_b   = (const float*)d_in[17];
    const float* ff_w1  = (const float*)d_in[18];
    const float* ff_b1  = (const float*)d_in[19];
    const float* ff_w2  = (const float*)d_in[20];
    const float* ff_b2  = (const float*)d_in[21];
    const float* cff_g  = (const float*)d_in[22];
    const float* cff_b  = (const float*)d_in[23];
    const float* cff_w1 = (const float*)d_in[24];
    const float* cff_b1 = (const float*)d_in[25];
    const float* cff_w2 = (const float*)d_in[26];
    const float* cff_b2 = (const float*)d_in[27];
    float* outp = (float*)d_out;

    float *xn, *cn, *qk, *v, *cqk, *cv, *sim, *attn, *cattn, *out, *cout, *x1, *c1, *hbuf;
    cudaGetSymbolAddress((void**)&xn,    g_xn);
    cudaGetSymbolAddress((void**)&cn,    g_cn);
    cudaGetSymbolAddress((void**)&qk,    g_qk);
    cudaGetSymbolAddress((void**)&v,     g_v);
    cudaGetSymbolAddress((void**)&cqk,   g_cqk);
    cudaGetSymbolAddress((void**)&cv,    g_cv);
    cudaGetSymbolAddress((void**)&sim,   g_sim);
    cudaGetSymbolAddress((void**)&attn,  g_attn);
    cudaGetSymbolAddress((void**)&cattn, g_cattn);
    cudaGetSymbolAddress((void**)&out,   g_out);
    cudaGetSymbolAddress((void**)&cout,  g_cout);
    cudaGetSymbolAddress((void**)&x1,    g_x1);
    cudaGetSymbolAddress((void**)&c1,    g_c1);
    cudaGetSymbolAddress((void**)&hbuf,  g_h);

    const float SCALE = 0.125f;   // DH^-0.5 = 64^-0.5

    // 0) detect mask dtype (bool/int32/float32)
    detect_mask_mode<<<1, 256>>>((const float*)mask, (Bb * Nn) / 4);

    // 1) pre-norm
    ln_k<<<Bb * Nn,  256>>>(x,   ln_x_g, ln_x_b, xn, Dd);
    ln_k<<<Bb * MM_, 256>>>(ctx, ln_c_g, ln_c_b, cn, Dd);

    // 2) projections (M=B*N rows, N=INNER, K=D)
    LAUNCH_GEMM(128, 128, false, false, 0,
                dim3(INNERi / 128, Bb * Nn / 128, 1),
                xn, Dd, 0, 0, W_qk, INNERi, 0, 0, qk, INNERi, 0, 0,
                nullptr, nullptr, 0, Dd, 1.f, 1);
    LAUNCH_GEMM(128, 128, false, false, 0,
                dim3(INNERi / 128, Bb * Nn / 128, 1),
                xn, Dd, 0, 0, W_v, INNERi, 0, 0, v, INNERi, 0, 0,
                nullptr, nullptr, 0, Dd, 1.f, 1);
    LAUNCH_GEMM(128, 128, false, false, 0,
                dim3(INNERi / 128, Bb * MM_ / 128, 1),
                cn, Dd, 0, 0, Wc_qk, INNERi, 0, 0, cqk, INNERi, 0, 0,
                nullptr, nullptr, 0, Dd, 1.f, 1);
    LAUNCH_GEMM(128, 128, false, false, 0,
                dim3(INNERi / 128, Bb * MM_ / 128, 1),
                cn, Dd, 0, 0, Wc_v, INNERi, 0, 0, cv, INNERi, 0, 0,
                nullptr, nullptr, 0, Dd, 1.f, 1);

    // 3) sim[b,h] = qk[b,:,h,:] @ cqk[b,:,h,:]^T * SCALE   (batched over b*h)
    LAUNCH_GEMM(128, 128, false, true, 0,
                dim3(MM_ / 128, Nn / 128, Bb * Hh),
                qk,  INNERi, (long)Nn  * INNERi, DHd,
                cqk, INNERi, (long)MM_ * INNERi, DHd,
                sim, MM_,    (long)Hh * Nn * MM_, (long)Nn * MM_,
                nullptr, nullptr, 0, DHd, SCALE, Hh);

    // 4) dual softmax
    softmax_row<<<Bb * Hh * Nn, 256>>>(sim, attn, mask, cmask);
    softmax_col<<<dim3(MM_ / 32, Bb * Hh), 256>>>(sim, cattn, mask, cmask);

    // 5) out = attn @ cv ;  cout = cattn^T @ v   (N = DH = 64)
    LAUNCH_GEMM(128, 64, false, false, 0,
                dim3(1, Nn / 128, Bb * Hh),
                attn, MM_,   (long)Hh * Nn * MM_, (long)Nn * MM_,
                cv,  INNERi, (long)MM_ * INNERi, DHd,
                out, INNERi, (long)Nn  * INNERi, DHd,
                nullptr, nullptr, 0, MM_, 1.f, Hh);
    LAUNCH_GEMM(128, 64, true, false, 0,
                dim3(1, MM_ / 128, Bb * Hh),
                cattn, MM_,  (long)Hh * Nn * MM_, (long)Nn * MM_,
                v,   INNERi, (long)Nn  * INNERi, DHd,
                cout, INNERi, (long)MM_ * INNERi, DHd,
                nullptr, nullptr, 0, Nn, 1.f, Hh);

    // 6) output projection + residual
    LAUNCH_GEMM(128, 128, false, false, 2,
                dim3(Dd / 128, Bb * Nn / 128, 1),
                out, INNERi, 0, 0, W_out, Dd, 0, 0, x1, Dd, 0, 0,
                b_out, x, Dd, INNERi, 1.f, 1);
    LAUNCH_GEMM(128, 128, false, false, 2,
                dim3(Dd / 128, Bb * MM_ / 128, 1),
                cout, INNERi, 0, 0, Wc_out, Dd, 0, 0, c1, Dd, 0, 0,
                bc_out, ctx, Dd, INNERi, 1.f, 1);

    // 7) FFN (x side) -> d_out[0 : B*N*D)
    ln_k<<<Bb * Nn, 256>>>(x1, ff_g, ff_b, xn, Dd);
    LAUNCH_GEMM(128, 128, false, false, 3,
                dim3(FFDf / 128, Bb * Nn / 128, 1),
                xn, Dd, 0, 0, ff_w1, FFDf, 0, 0, hbuf, FFDf, 0, 0,
                ff_b1, nullptr, 0, Dd, 1.f, 1);
    LAUNCH_GEMM(128, 128, false, false, 2,
                dim3(Dd / 128, Bb * Nn / 128, 1),
                hbuf, FFDf, 0, 0, ff_w2, Dd, 0, 0, outp, Dd, 0, 0,
                ff_b2, x1, Dd, FFDf, 1.f, 1);

    // 8) FFN (context side) -> d_out[B*N*D : 2*B*N*D)
    ln_k<<<Bb * MM_, 256>>>(c1, cff_g, cff_b, cn, Dd);
    LAUNCH_GEMM(128, 128, false, false, 3,
                dim3(FFDf / 128, Bb * MM_ / 128, 1),
                cn, Dd, 0, 0, cff_w1, FFDf, 0, 0, hbuf, FFDf, 0, 0,
                cff_b1, nullptr, 0, Dd, 1.f, 1);
    LAUNCH_GEMM(128, 128, false, false, 2,
                dim3(Dd / 128, Bb * MM_ / 128, 1),
                hbuf, FFDf, 0, 0, cff_w2, Dd, 0, 0, outp + (long)Bb * Nn * Dd, Dd, 0, 0,
                cff_b2, c1, Dd, FFDf, 1.f, 1);
}

// round 5
// speedup vs baseline: 2.0343x; 1.0879x over previous
#include <cuda_runtime.h>
#include <mma.h>
#include <math.h>

using namespace nvcuda;

#define Bb 2
#define Nn 2048
#define MM_ 2048
#define Dd 1024
#define Hh 8
#define DHd 64
#define INNERi 512
#define FFDf 4096

// ---------------- scratch (device globals; no cudaMalloc allowed) ----------
__device__ __align__(256) float g_xn [Bb*Nn*Dd];
__device__ __align__(256) float g_cn [Bb*MM_*Dd];
__device__ __align__(256) float g_qk [Bb*Nn*INNERi];
__device__ __align__(256) float g_v  [Bb*Nn*INNERi];
__device__ __align__(256) float g_cqk[Bb*MM_*INNERi];
__device__ __align__(256) float g_cv [Bb*MM_*INNERi];
__device__ __align__(256) float g_sim  [Bb*Hh*Nn*MM_];
__device__ __align__(256) float g_attn [Bb*Hh*Nn*MM_];
__device__ __align__(256) float g_cattn[Bb*Hh*Nn*MM_];
__device__ __align__(256) float g_out [Bb*Nn*INNERi];
__device__ __align__(256) float g_cout[Bb*MM_*INNERi];
__device__ __align__(256) float g_x1  [Bb*Nn*Dd];
__device__ __align__(256) float g_c1  [Bb*MM_*Dd];
__device__ __align__(256) float g_h   [Bb*Nn*FFDf];
__device__ int   g_mask_mode;   // 0 = u8/bool, 1 = int32, 2 = float32

// ---------------- mask dtype detection ------------------------------------
__global__ void detect_mask_mode(const float* __restrict__ fp, int n4)
{
    __shared__ int okf_s, oki_s;
    if (threadIdx.x == 0) { okf_s = 1; oki_s = 1; }
    __syncthreads();
    const int* ip = (const int*)fp;
    bool okf = true, oki = true;
    for (int i = threadIdx.x; i < n4; i += 256) {
        float fv = fp[i]; okf = okf && (fv == 0.f || fv == 1.f);
        int   iv = ip[i]; oki = oki && (iv == 0 || iv == 1);
    }
    if (!okf) atomicAnd(&okf_s, 0);
    if (!oki) atomicAnd(&oki_s, 0);
    __syncthreads();
    if (threadIdx.x == 0) g_mask_mode = okf_s ? 2 : (oki_s ? 1 : 0);
}

__device__ __forceinline__ bool mask_at(const void* m, int i, int mode)
{
    if (mode == 1) return ((const int*)m)[i] != 0;
    if (mode == 2) return ((const float*)m)[i] != 0.f;
    return ((const unsigned char*)m)[i] != 0;
}

// ---------------- LayerNorm --------------------------------------------
__global__ __launch_bounds__(256)
void ln_k(const float* __restrict__ in, const float* __restrict__ g,
          const float* __restrict__ b, float* __restrict__ out, int cols)
{
    __shared__ float r1[256], r2[256];
    long row = blockIdx.x;
    const float* p = in + row * cols;
    float* o = out + row * cols;
    int tid = threadIdx.x;
    float s = 0.f, s2 = 0.f;
    for (int c = tid; c < cols; c += 256) { float v = p[c]; s += v; s2 += v * v; }
    r1[tid] = s; r2[tid] = s2; __syncthreads();
    for (int st = 128; st > 0; st >>= 1) {
        if (tid < st) { r1[tid] += r1[tid + st]; r2[tid] += r2[tid + st]; }
        __syncthreads();
    }
    float mu  = r1[0] / cols;
    float var = r2[0] / cols - mu * mu;
    float inv = rsqrtf(var + 1e-5f);
    for (int c = tid; c < cols; c += 256)
        o[c] = (p[c] - mu) * inv * g[c] + b[c];
}

// ---------------- Row softmax (over j, length MM_) ----------------------
__global__ __launch_bounds__(256)
void softmax_row(const float* __restrict__ sim, float* __restrict__ attn,
                 const void* __restrict__ mask,
                 const void* __restrict__ cmask)
{
    __shared__ float buf[MM_];
    __shared__ float red[256];
    int mode = g_mask_mode;
    long row = blockIdx.x;             // (b*H + h)*N + i
    int i  = (int)(row % Nn);
    int bh = (int)(row / Nn);
    int b  = bh / Hh;
    const float* src = sim  + row * (long)MM_;
    float*       dst = attn + row * (long)MM_;
    int tid = threadIdx.x;
    bool mi = mask_at(mask, b * Nn + i, mode);

    float lmax = -3.402823466e38f;
    for (int j = tid; j < MM_; j += 256) {
        bool mj = mask_at(cmask, b * MM_ + j, mode);
        float vv = (mi && mj) ? src[j] : -3.402823466e38f;
        buf[j] = vv;
        lmax = fmaxf(lmax, vv);
    }
    red[tid] = lmax; __syncthreads();
    for (int s = 128; s > 0; s >>= 1) {
        if (tid < s) red[tid] = fmaxf(red[tid], red[tid + s]);
        __syncthreads();
    }
    float rmax = red[0]; __syncthreads();
    float lsum = 0.f;
    for (int j = tid; j < MM_; j += 256) {
        float e = expf(buf[j] - rmax);
        buf[j] = e; lsum += e;
    }
    red[tid] = lsum; __syncthreads();
    for (int s = 128; s > 0; s >>= 1) {
        if (tid < s) red[tid] += red[tid + s];
        __syncthreads();
    }
    float inv = 1.f / red[0];
    for (int j = tid; j < MM_; j += 256) dst[j] = buf[j] * inv;
}

// ---------------- Column softmax (over i) --------------------------------
__global__ __launch_bounds__(256)
void softmax_col(const float* __restrict__ sim, float* __restrict__ cattn,
                 const void* __restrict__ mask,
                 const void* __restrict__ cmask)
{
    __shared__ float sm[8][32], ss[8][32];
    int mode = g_mask_mode;
    int z = blockIdx.y;                // b*H + h
    int b = z / Hh;
    int c = threadIdx.x & 31;
    int g = threadIdx.x >> 5;
    int j = blockIdx.x * 32 + c;
    const float* base = sim   + (long)z * Nn * MM_;
    float*       outb = cattn + (long)z * Nn * MM_;
    bool mj = mask_at(cmask, b * MM_ + j, mode);

    float m = -3.402823466e38f, s = 0.f;
    for (int i = g; i < Nn; i += 8) {
        bool mi = mask_at(mask, b * Nn + i, mode);
        float vv = (mj && mi) ? base[(long)i * MM_ + j] : -3.402823466e38f;
        if (vv > m) { s = s * expf(m - vv) + 1.f; m = vv; }
        else        { s += expf(vv - m); }
    }
    sm[g][c] = m; ss[g][c] = s; __syncthreads();
    if (g == 0) {
        float Mloc = sm[0][c], Sloc = ss[0][c];
        #pragma unroll
        for (int t = 1; t < 8; t++) {
            float mt = sm[t][c], st = ss[t][c];
            float nm = fmaxf(Mloc, mt);
            Sloc = Sloc * expf(Mloc - nm) + st * expf(mt - nm);
            Mloc = nm;
        }
        sm[0][c] = Mloc; ss[0][c] = 1.f / Sloc;
    }
    __syncthreads();
    float Mg = sm[0][c], inv = ss[0][c];
    for (int i = g; i < Nn; i += 8) {
        bool mi = mask_at(mask, b * Nn + i, mode);
        float vv = (mj && mi) ? base[(long)i * MM_ + j] : -3.402823466e38f;
        outb[(long)i * MM_ + j] = expf(vv - Mg) * inv;
    }
}

// ---------------- cp.async helpers -----------------------------------------
__device__ __forceinline__ void cpa16(float* dst, const float* src)
{
    unsigned d = (unsigned)__cvta_generic_to_shared(dst);
    asm volatile("cp.async.cg.shared.global [%0], [%1], 16;\n" :: "r"(d), "l"(src));
}

// ---------------- TF32 WMMA GEMM, 3-stage cp.async pipeline ----------------
// C(MxN) = alpha * op(A)(MxK) @ op(B)(KxN) [+ bias[n] + res[m,n]] [gelu]
// Block tile BMxBN, K-tile 32, 256 threads (8 warps), 2 CTAs/SM.
// One __syncthreads per k-tile: stage kt+2 is loaded after the sync, into the
// buffer all warps vacated at iteration kt-1.
// AC/BC: operand transposed in memory -> smem col-major + col_major fragments.
// EPI: 0 = alpha, direct frag store; 2 = bias+residual; 3 = bias+exact GELU.
template<int BM, int BN, bool AC, bool BC, int EPI>
__global__ __launch_bounds__(256, 2)
void gemm2(const float* __restrict__ A, int lda, long aO, long aI,
           const float* __restrict__ Bm, int ldb, long bO, long bI,
           float* __restrict__ C, int ldc, long cO, long cI,
           const float* __restrict__ bias,
           const float* __restrict__ res, int ldr,
           int K, float alpha, int HHd)
{
    constexpr int BK   = 32;
    constexpr int NST  = 3;
    constexpr int LDAS = AC ? BM + 4 : BK + 4;
    constexpr int AEL  = AC ? BK * LDAS : BM * LDAS;
    constexpr int LDBS = BC ? BK + 4 : BN + 4;
    constexpr int BEL  = BC ? BN * LDBS : BK * LDBS;
    constexpr int WRM  = (BN == 128) ? 2 : 4;
    constexpr int WRN  = 8 / WRM;
    constexpr int TM   = BM / WRM;
    constexpr int TN   = BN / WRN;
    constexpr int FM   = TM / 16;
    constexpr int FN   = TN / 16;
    constexpr int LDCS = BN + 4;

    extern __shared__ float sm_[];
    float* sA = sm_;
    float* sB = sm_ + NST * AEL;
    float* sC = sm_;   // epilogue staging aliases pipeline buffers

    int z  = blockIdx.z;
    int zo = z / HHd, zi = z % HHd;
    A  += (long)zo * aO + (long)zi * aI;
    Bm += (long)zo * bO + (long)zi * bI;
    C  += (long)zo * cO + (long)zi * cI;

    int m0 = blockIdx.y * BM;
    int n0 = blockIdx.x * BN;
    int tid  = threadIdx.x;
    int warp = tid >> 5;
    int wm0 = (warp % WRM) * TM;
    int wn0 = (warp / WRM) * TN;

    auto load_stage = [&](int s, int kt) {
        float* sAs = sA + s * AEL;
        float* sBs = sB + s * BEL;
        if (!AC) {
            constexpr int IT = (BM * (BK / 4)) / 256;
            #pragma unroll
            for (int t = 0; t < IT; t++) {
                int idx = t * 256 + tid;
                int r = idx >> 3, c = idx & 7;
                cpa16(sAs + r * LDAS + c * 4,
                      A + (long)(m0 + r) * lda + kt + c * 4);
            }
        } else {
            constexpr int PR = BM / 4;
            constexpr int IT = (BK * PR) / 256;
            #pragma unroll
            for (int t = 0; t < IT; t++) {
                int idx = t * 256 + tid;
                int k = idx / PR, mc = idx % PR;
                cpa16(sAs + k * LDAS + mc * 4,
                      A + (long)(kt + k) * lda + m0 + mc * 4);
            }
        }
        if (!BC) {
            constexpr int PR = BN / 4;
            constexpr int IT = (BK * PR) / 256;
            #pragma unroll
            for (int t = 0; t < IT; t++) {
                int idx = t * 256 + tid;
                int r = idx / PR, c = idx % PR;
                cpa16(sBs + r * LDBS + c * 4,
                      Bm + (long)(kt + r) * ldb + n0 + c * 4);
            }
        } else {
            constexpr int IT = (BN * (BK / 4)) / 256;
            #pragma unroll
            for (int t = 0; t < IT; t++) {
                int idx = t * 256 + tid;
                int n = idx >> 3, c = idx & 7;
                cpa16(sBs + n * LDBS + c * 4,
                      Bm + (long)(n0 + n) * ldb + kt + c * 4);
            }
        }
        asm volatile("cp.async.commit_group;\n");
    };

    using ALay = typename std::conditional<AC, wmma::col_major, wmma::row_major>::type;
    using BLay = typename std::conditional<BC, wmma::col_major, wmma::row_major>::type;

    wmma::fragment<wmma::accumulator, 16, 16, 8, float> fc[FM][FN];
    #pragma unroll
    for (int i = 0; i < FM; i++)
        #pragma unroll
        for (int j = 0; j < FN; j++)
            wmma::fill_fragment(fc[i][j], 0.f);

    int T = K / BK;
    load_stage(0, 0);
    if (T > 1) load_stage(1, BK);

    for (int kt = 0; kt < T; kt++) {
        if (kt + 1 < T) asm volatile("cp.async.wait_group 1;\n");
        else            asm volatile("cp.async.wait_group 0;\n");
        __syncthreads();
        if (kt + 2 < T) load_stage((kt + 2) % NST, (kt + 2) * BK);

        int s = kt % NST;
        const float* sAs = sA + s * AEL;
        const float* sBs = sB + s * BEL;

        #pragma unroll
        for (int kk = 0; kk < BK; kk += 8) {
            wmma::fragment<wmma::matrix_a, 16, 16, 8, wmma::precision::tf32, ALay> fa[FM];
            wmma::fragment<wmma::matrix_b, 16, 16, 8, wmma::precision::tf32, BLay> fb[FN];
            #pragma unroll
            for (int i = 0; i < FM; i++) {
                const float* ap = AC ? (sAs + kk * LDAS + wm0 + i * 16)
                                     : (sAs + (wm0 + i * 16) * LDAS + kk);
                wmma::load_matrix_sync(fa[i], ap, LDAS);
                #pragma unroll
                for (int t = 0; t < fa[i].num_elements; t++)
                    fa[i].x[t] = wmma::__float_to_tf32(fa[i].x[t]);
            }
            #pragma unroll
            for (int j = 0; j < FN; j++) {
                const float* bp = BC ? (sBs + (wn0 + j * 16) * LDBS + kk)
                                     : (sBs + kk * LDBS + wn0 + j * 16);
                wmma::load_matrix_sync(fb[j], bp, LDBS);
                #pragma unroll
                for (int t = 0; t < fb[j].num_elements; t++)
                    fb[j].x[t] = wmma::__float_to_tf32(fb[j].x[t]);
            }
            #pragma unroll
            for (int i = 0; i < FM; i++)
                #pragma unroll
                for (int j = 0; j < FN; j++)
                    wmma::mma_sync(fc[i][j], fa[i], fb[j], fc[i][j]);
        }
    }

    if (EPI == 0) {
        #pragma unroll
        for (int i = 0; i < FM; i++)
            #pragma unroll
            for (int j = 0; j < FN; j++) {
                #pragma unroll
                for (int t = 0; t < fc[i][j].num_elements; t++)
                    fc[i][j].x[t] *= alpha;
                wmma::store_matrix_sync(
                    C + (long)(m0 + wm0 + i * 16) * ldc + n0 + wn0 + j * 16,
                    fc[i][j], ldc, wmma::mem_row_major);
            }
    } else {
        __syncthreads();   // all warps done with pipeline smem before aliasing
        #pragma unroll
        for (int i = 0; i < FM; i++)
            #pragma unroll
            for (int j = 0; j < FN; j++)
                wmma::store_matrix_sync(sC + (wm0 + i * 16) * LDCS + wn0 + j * 16,
                                        fc[i][j], LDCS, wmma::mem_row_major);
        __syncthreads();
        for (int idx = tid; idx < BM * BN; idx += 256) {
            int r = idx / BN, c = idx % BN;
            int gm = m0 + r, gn = n0 + c;
            float v = sC[r * LDCS + c];
            if (EPI == 2) v += bias[gn] + res[(long)gm * ldr + gn];
            if (EPI == 3) {
                v += bias[gn];
                v = 0.5f * v * (1.f + erff(v * 0.7071067811865476f));
            }
            C[(long)gm * ldc + gn] = v;
        }
    }
}

// host-side smem size (mirrors kernel constexprs)
static constexpr size_t smemb(int BM, int BN, bool AC, bool BC, int EPI)
{
    int LDAS = AC ? BM + 4 : 36;
    int AEL  = AC ? 32 * LDAS : BM * LDAS;
    int LDBS = BC ? 36 : BN + 4;
    int BEL  = BC ? BN * LDBS : 32 * LDBS;
    int pipe = 3 * (AEL + BEL);
    int epi  = EPI ? BM * (BN + 4) : 0;
    return 4u * (size_t)(pipe > epi ? pipe : epi);
}

#define LAUNCH_GEMM(BM, BN, AC, BC, EPI, grid, ...)                             \
    do {                                                                        \
        auto kfn = gemm2<BM, BN, AC, BC, EPI>;                                  \
        size_t smb = smemb(BM, BN, AC, BC, EPI);                                \
        cudaFuncSetAttribute(kfn, cudaFuncAttributeMaxDynamicSharedMemorySize,  \
                             (int)smb);                                         \
        kfn<<<grid, 256, smb>>>(__VA_ARGS__);                                   \
    } while (0)

// ---------------- host ----------------------------------------------------
extern "C" void kernel_launch(void* const* d_in, const int* in_sizes, int n_in,
                              void* d_out, int out_size)
{
    (void)in_sizes; (void)n_in; (void)out_size;
    const float* x      = (const float*)d_in[0];
    const float* ctx    = (const float*)d_in[1];
    const void*  mask   = d_in[2];
    const void*  cmask  = d_in[3];
    const float* ln_x_g = (const float*)d_in[4];
    const float* ln_x_b = (const float*)d_in[5];
    const float* ln_c_g = (const float*)d_in[6];
    const float* ln_c_b = (const float*)d_in[7];
    const float* W_qk   = (const float*)d_in[8];
    const float* W_v    = (const float*)d_in[9];
    const float* Wc_qk  = (const float*)d_in[10];
    const float* Wc_v   = (const float*)d_in[11];
    const float* W_out  = (const float*)d_in[12];
    const float* b_out  = (const float*)d_in[13];
    const float* Wc_out = (const float*)d_in[14];
    const float* bc_out = (const float*)d_in[15];
    const float* ff_g   = (const float*)d_in[16];
    const float* ff_b   = (const float*)d_in[17];
    const float* ff_w1  = (const float*)d_in[18];
    const float* ff_b1  = (const float*)d_in[19];
    const float* ff_w2  = (const float*)d_in[20];
    const float* ff_b2  = (const float*)d_in[21];
    const float* cff_g  = (const float*)d_in[22];
    const float* cff_b  = (const float*)d_in[23];
    const float* cff_w1 = (const float*)d_in[24];
    const float* cff_b1 = (const float*)d_in[25];
    const float* cff_w2 = (const float*)d_in[26];
    const float* cff_b2 = (const float*)d_in[27];
    float* outp = (float*)d_out;

    float *xn, *cn, *qk, *v, *cqk, *cv, *sim, *attn, *cattn, *out, *cout, *x1, *c1, *hbuf;
    cudaGetSymbolAddress((void**)&xn,    g_xn);
    cudaGetSymbolAddress((void**)&cn,    g_cn);
    cudaGetSymbolAddress((void**)&qk,    g_qk);
    cudaGetSymbolAddress((void**)&v,     g_v);
    cudaGetSymbolAddress((void**)&cqk,   g_cqk);
    cudaGetSymbolAddress((void**)&cv,    g_cv);
    cudaGetSymbolAddress((void**)&sim,   g_sim);
    cudaGetSymbolAddress((void**)&attn,  g_attn);
    cudaGetSymbolAddress((void**)&cattn, g_cattn);
    cudaGetSymbolAddress((void**)&out,   g_out);
    cudaGetSymbolAddress((void**)&cout,  g_cout);
    cudaGetSymbolAddress((void**)&x1,    g_x1);
    cudaGetSymbolAddress((void**)&c1,    g_c1);
    cudaGetSymbolAddress((void**)&hbuf,  g_h);

    const float SCALE = 0.125f;   // DH^-0.5 = 64^-0.5

    // 0) detect mask dtype (bool/int32/float32)
    detect_mask_mode<<<1, 256>>>((const float*)mask, (Bb * Nn) / 4);

    // 1) pre-norm
    ln_k<<<Bb * Nn,  256>>>(x,   ln_x_g, ln_x_b, xn, Dd);
    ln_k<<<Bb * MM_, 256>>>(ctx, ln_c_g, ln_c_b, cn, Dd);

    // 2) projections (BM=64 so grid >= 256 blocks: full SM coverage)
    LAUNCH_GEMM(64, 128, false, false, 0,
                dim3(INNERi / 128, Bb * Nn / 64, 1),
                xn, Dd, 0, 0, W_qk, INNERi, 0, 0, qk, INNERi, 0, 0,
                nullptr, nullptr, 0, Dd, 1.f, 1);
    LAUNCH_GEMM(64, 128, false, false, 0,
                dim3(INNERi / 128, Bb * Nn / 64, 1),
                xn, Dd, 0, 0, W_v, INNERi, 0, 0, v, INNERi, 0, 0,
                nullptr, nullptr, 0, Dd, 1.f, 1);
    LAUNCH_GEMM(64, 128, false, false, 0,
                dim3(INNERi / 128, Bb * MM_ / 64, 1),
                cn, Dd, 0, 0, Wc_qk, INNERi, 0, 0, cqk, INNERi, 0, 0,
                nullptr, nullptr, 0, Dd, 1.f, 1);
    LAUNCH_GEMM(64, 128, false, false, 0,
                dim3(INNERi / 128, Bb * MM_ / 64, 1),
                cn, Dd, 0, 0, Wc_v, INNERi, 0, 0, cv, INNERi, 0, 0,
                nullptr, nullptr, 0, Dd, 1.f, 1);

    // 3) sim[b,h] = qk[b,:,h,:] @ cqk[b,:,h,:]^T * SCALE   (batched over b*h)
    LAUNCH_GEMM(128, 128, false, true, 0,
                dim3(MM_ / 128, Nn / 128, Bb * Hh),
                qk,  INNERi, (long)Nn  * INNERi, DHd,
                cqk, INNERi, (long)MM_ * INNERi, DHd,
                sim, MM_,    (long)Hh * Nn * MM_, (long)Nn * MM_,
                nullptr, nullptr, 0, DHd, SCALE, Hh);

    // 4) dual softmax
    softmax_row<<<Bb * Hh * Nn, 256>>>(sim, attn, mask, cmask);
    softmax_col<<<dim3(MM_ / 32, Bb * Hh), 256>>>(sim, cattn, mask, cmask);

    // 5) out = attn @ cv ;  cout = cattn^T @ v   (N = DH = 64)
    LAUNCH_GEMM(128, 64, false, false, 0,
                dim3(1, Nn / 128, Bb * Hh),
                attn, MM_,   (long)Hh * Nn * MM_, (long)Nn * MM_,
                cv,  INNERi, (long)MM_ * INNERi, DHd,
                out, INNERi, (long)Nn  * INNERi, DHd,
                nullptr, nullptr, 0, MM_, 1.f, Hh);
    LAUNCH_GEMM(128, 64, true, false, 0,
                dim3(1, MM_ / 128, Bb * Hh),
                cattn, MM_,  (long)Hh * Nn * MM_, (long)Nn * MM_,
                v,   INNERi, (long)Nn  * INNERi, DHd,
                cout, INNERi, (long)MM_ * INNERi, DHd,
                nullptr, nullptr, 0, Nn, 1.f, Hh);

    // 6) output projection + residual
    LAUNCH_GEMM(128, 128, false, false, 2,
                dim3(Dd / 128, Bb * Nn / 128, 1),
                out, INNERi, 0, 0, W_out, Dd, 0, 0, x1, Dd, 0, 0,
                b_out, x, Dd, INNERi, 1.f, 1);
    LAUNCH_GEMM(128, 128, false, false, 2,
                dim3(Dd / 128, Bb * MM_ / 128, 1),
                cout, INNERi, 0, 0, Wc_out, Dd, 0, 0, c1, Dd, 0, 0,
                bc_out, ctx, Dd, INNERi, 1.f, 1);

    // 7) FFN (x side) -> d_out[0 : B*N*D)
    ln_k<<<Bb * Nn, 256>>>(x1, ff_g, ff_b, xn, Dd);
    LAUNCH_GEMM(128, 128, false, false, 3,
                dim3(FFDf / 128, Bb * Nn / 128, 1),
                xn, Dd, 0, 0, ff_w1, FFDf, 0, 0, hbuf, FFDf, 0, 0,
                ff_b1, nullptr, 0, Dd, 1.f, 1);
    LAUNCH_GEMM(128, 128, false, false, 2,
                dim3(Dd / 128, Bb * Nn / 128, 1),
                hbuf, FFDf, 0, 0, ff_w2, Dd, 0, 0, outp, Dd, 0, 0,
                ff_b2, x1, Dd, FFDf, 1.f, 1);

    // 8) FFN (context side) -> d_out[B*N*D : 2*B*N*D)
    ln_k<<<Bb * MM_, 256>>>(c1, cff_g, cff_b, cn, Dd);
    LAUNCH_GEMM(128, 128, false, false, 3,
                dim3(FFDf / 128, Bb * MM_ / 128, 1),
                cn, Dd, 0, 0, cff_w1, FFDf, 0, 0, hbuf, FFDf, 0, 0,
                cff_b1, nullptr, 0, Dd, 1.f, 1);
    LAUNCH_GEMM(128, 128, false, false, 2,
                dim3(Dd / 128, Bb * MM_ / 128, 1),
                hbuf, FFDf, 0, 0, cff_w2, Dd, 0, 0, outp + (long)Bb * Nn * Dd, Dd, 0, 0,
                cff_b2, c1, Dd, FFDf, 1.f, 1);
}

// round 6
// speedup vs baseline: 2.1185x; 1.0414x over previous
#include <cuda_runtime.h>
#include <mma.h>
#include <math.h>

using namespace nvcuda;

#define Bb 2
#define Nn 2048
#define MM_ 2048
#define Dd 1024
#define Hh 8
#define DHd 64
#define INNERi 512
#define FFDf 4096

// ---------------- scratch (device globals; no cudaMalloc allowed) ----------
__device__ __align__(256) float g_xn [Bb*Nn*Dd];
__device__ __align__(256) float g_cn [Bb*MM_*Dd];
__device__ __align__(256) float g_qk [Bb*Nn*INNERi];
__device__ __align__(256) float g_v  [Bb*Nn*INNERi];
__device__ __align__(256) float g_cqk[Bb*MM_*INNERi];
__device__ __align__(256) float g_cv [Bb*MM_*INNERi];
__device__ __align__(256) float g_sim  [Bb*Hh*Nn*MM_];
__device__ __align__(256) float g_attn [Bb*Hh*Nn*MM_];
__device__ __align__(256) float g_cattn[Bb*Hh*Nn*MM_];
__device__ __align__(256) float g_out [Bb*Nn*INNERi];
__device__ __align__(256) float g_cout[Bb*MM_*INNERi];
__device__ __align__(256) float g_x1  [Bb*Nn*Dd];
__device__ __align__(256) float g_c1  [Bb*MM_*Dd];
__device__ __align__(256) float g_h   [Bb*Nn*FFDf];
__device__ __align__(256) float g_wr [19922944];   // tf32-rounded weights
__device__ int   g_mask_mode;   // 0 = u8/bool, 1 = int32, 2 = float32

// rounded-weight offsets in g_wr
#define OFF_WQK   0L
#define OFF_WV    524288L
#define OFF_WCQK  1048576L
#define OFF_WCV   1572864L
#define OFF_WOUT  2097152L
#define OFF_WCOUT 2621440L
#define OFF_FFW1  3145728L
#define OFF_FFW2  7340032L
#define OFF_CFFW1 11534336L
#define OFF_CFFW2 15728640L

__device__ __forceinline__ float tf32r(float x)
{
    float r;
    asm("cvt.rna.tf32.f32 %0, %1;" : "=f"(r) : "f"(x));
    return r;
}

// ---------------- tf32 rounding copy (weights) ------------------------------
__global__ __launch_bounds__(256)
void tf32_round_k(const float4* __restrict__ in, float4* __restrict__ out, int n4)
{
    for (int i = blockIdx.x * 256 + threadIdx.x; i < n4; i += gridDim.x * 256) {
        float4 v = in[i];
        v.x = tf32r(v.x); v.y = tf32r(v.y);
        v.z = tf32r(v.z); v.w = tf32r(v.w);
        out[i] = v;
    }
}

// ---------------- mask dtype detection ------------------------------------
__global__ void detect_mask_mode(const float* __restrict__ fp, int n4)
{
    __shared__ int okf_s, oki_s;
    if (threadIdx.x == 0) { okf_s = 1; oki_s = 1; }
    __syncthreads();
    const int* ip = (const int*)fp;
    bool okf = true, oki = true;
    for (int i = threadIdx.x; i < n4; i += 256) {
        float fv = fp[i]; okf = okf && (fv == 0.f || fv == 1.f);
        int   iv = ip[i]; oki = oki && (iv == 0 || iv == 1);
    }
    if (!okf) atomicAnd(&okf_s, 0);
    if (!oki) atomicAnd(&oki_s, 0);
    __syncthreads();
    if (threadIdx.x == 0) g_mask_mode = okf_s ? 2 : (oki_s ? 1 : 0);
}

__device__ __forceinline__ bool mask_at(const void* m, int i, int mode)
{
    if (mode == 1) return ((const int*)m)[i] != 0;
    if (mode == 2) return ((const float*)m)[i] != 0.f;
    return ((const unsigned char*)m)[i] != 0;
}

// ---------------- LayerNorm (output rounded to tf32) -----------------------
__global__ __launch_bounds__(256)
void ln_k(const float* __restrict__ in, const float* __restrict__ g,
          const float* __restrict__ b, float* __restrict__ out, int cols)
{
    __shared__ float r1[256], r2[256];
    long row = blockIdx.x;
    const float* p = in + row * cols;
    float* o = out + row * cols;
    int tid = threadIdx.x;
    float s = 0.f, s2 = 0.f;
    for (int c = tid; c < cols; c += 256) { float v = p[c]; s += v; s2 += v * v; }
    r1[tid] = s; r2[tid] = s2; __syncthreads();
    for (int st = 128; st > 0; st >>= 1) {
        if (tid < st) { r1[tid] += r1[tid + st]; r2[tid] += r2[tid + st]; }
        __syncthreads();
    }
    float mu  = r1[0] / cols;
    float var = r2[0] / cols - mu * mu;
    float inv = rsqrtf(var + 1e-5f);
    for (int c = tid; c < cols; c += 256)
        o[c] = tf32r((p[c] - mu) * inv * g[c] + b[c]);
}

// ---------------- Row softmax (output rounded to tf32) ---------------------
__global__ __launch_bounds__(256)
void softmax_row(const float* __restrict__ sim, float* __restrict__ attn,
                 const void* __restrict__ mask,
                 const void* __restrict__ cmask)
{
    __shared__ float buf[MM_];
    __shared__ float red[256];
    int mode = g_mask_mode;
    long row = blockIdx.x;             // (b*H + h)*N + i
    int i  = (int)(row % Nn);
    int bh = (int)(row / Nn);
    int b  = bh / Hh;
    const float* src = sim  + row * (long)MM_;
    float*       dst = attn + row * (long)MM_;
    int tid = threadIdx.x;
    bool mi = mask_at(mask, b * Nn + i, mode);

    float lmax = -3.402823466e38f;
    for (int j = tid; j < MM_; j += 256) {
        bool mj = mask_at(cmask, b * MM_ + j, mode);
        float vv = (mi && mj) ? src[j] : -3.402823466e38f;
        buf[j] = vv;
        lmax = fmaxf(lmax, vv);
    }
    red[tid] = lmax; __syncthreads();
    for (int s = 128; s > 0; s >>= 1) {
        if (tid < s) red[tid] = fmaxf(red[tid], red[tid + s]);
        __syncthreads();
    }
    float rmax = red[0]; __syncthreads();
    float lsum = 0.f;
    for (int j = tid; j < MM_; j += 256) {
        float e = expf(buf[j] - rmax);
        buf[j] = e; lsum += e;
    }
    red[tid] = lsum; __syncthreads();
    for (int s = 128; s > 0; s >>= 1) {
        if (tid < s) red[tid] += red[tid + s];
        __syncthreads();
    }
    float inv = 1.f / red[0];
    for (int j = tid; j < MM_; j += 256) dst[j] = tf32r(buf[j] * inv);
}

// ---------------- Column softmax (output rounded to tf32) ------------------
__global__ __launch_bounds__(256)
void softmax_col(const float* __restrict__ sim, float* __restrict__ cattn,
                 const void* __restrict__ mask,
                 const void* __restrict__ cmask)
{
    __shared__ float sm[8][32], ss[8][32];
    int mode = g_mask_mode;
    int z = blockIdx.y;                // b*H + h
    int b = z / Hh;
    int c = threadIdx.x & 31;
    int g = threadIdx.x >> 5;
    int j = blockIdx.x * 32 + c;
    const float* base = sim   + (long)z * Nn * MM_;
    float*       outb = cattn + (long)z * Nn * MM_;
    bool mj = mask_at(cmask, b * MM_ + j, mode);

    float m = -3.402823466e38f, s = 0.f;
    for (int i = g; i < Nn; i += 8) {
        bool mi = mask_at(mask, b * Nn + i, mode);
        float vv = (mj && mi) ? base[(long)i * MM_ + j] : -3.402823466e38f;
        if (vv > m) { s = s * expf(m - vv) + 1.f; m = vv; }
        else        { s += expf(vv - m); }
    }
    sm[g][c] = m; ss[g][c] = s; __syncthreads();
    if (g == 0) {
        float Mloc = sm[0][c], Sloc = ss[0][c];
        #pragma unroll
        for (int t = 1; t < 8; t++) {
            float mt = sm[t][c], st = ss[t][c];
            float nm = fmaxf(Mloc, mt);
            Sloc = Sloc * expf(Mloc - nm) + st * expf(mt - nm);
            Mloc = nm;
        }
        sm[0][c] = Mloc; ss[0][c] = 1.f / Sloc;
    }
    __syncthreads();
    float Mg = sm[0][c], inv = ss[0][c];
    for (int i = g; i < Nn; i += 8) {
        bool mi = mask_at(mask, b * Nn + i, mode);
        float vv = (mj && mi) ? base[(long)i * MM_ + j] : -3.402823466e38f;
        outb[(long)i * MM_ + j] = tf32r(expf(vv - Mg) * inv);
    }
}

// ---------------- cp.async helpers -----------------------------------------
__device__ __forceinline__ void cpa16(float* dst, const float* src)
{
    unsigned d = (unsigned)__cvta_generic_to_shared(dst);
    asm volatile("cp.async.cg.shared.global [%0], [%1], 16;\n" :: "r"(d), "l"(src));
}

// ---------------- TF32 WMMA GEMM, 3-stage cp.async pipeline ----------------
// ALL operands are pre-rounded to tf32 by their producers, so the hot loop
// issues NO cvt instructions (HW truncation of rounded values is identity).
// Block tile BMxBN, K-tile 32, 256 threads (8 warps), 2 CTAs/SM, one
// __syncthreads per k-tile.
// EPI: 0 = alpha (+opt tf32-round) direct frag store;
//      2 = bias+residual; 3 = bias+exact GELU (+opt tf32-round).
template<int BM, int BN, bool AC, bool BC, int EPI, bool RND>
__global__ __launch_bounds__(256, 2)
void gemm2(const float* __restrict__ A, int lda, long aO, long aI,
           const float* __restrict__ Bm, int ldb, long bO, long bI,
           float* __restrict__ C, int ldc, long cO, long cI,
           const float* __restrict__ bias,
           const float* __restrict__ res, int ldr,
           int K, float alpha, int HHd)
{
    constexpr int BK   = 32;
    constexpr int NST  = 3;
    constexpr int LDAS = AC ? BM + 4 : BK + 4;
    constexpr int AEL  = AC ? BK * LDAS : BM * LDAS;
    constexpr int LDBS = BC ? BK + 4 : BN + 4;
    constexpr int BEL  = BC ? BN * LDBS : BK * LDBS;
    constexpr int WRM  = (BN == 128) ? 2 : 4;
    constexpr int WRN  = 8 / WRM;
    constexpr int TM   = BM / WRM;
    constexpr int TN   = BN / WRN;
    constexpr int FM   = TM / 16;
    constexpr int FN   = TN / 16;
    constexpr int LDCS = BN + 4;

    extern __shared__ float sm_[];
    float* sA = sm_;
    float* sB = sm_ + NST * AEL;
    float* sC = sm_;   // epilogue staging aliases pipeline buffers

    int z  = blockIdx.z;
    int zo = z / HHd, zi = z % HHd;
    A  += (long)zo * aO + (long)zi * aI;
    Bm += (long)zo * bO + (long)zi * bI;
    C  += (long)zo * cO + (long)zi * cI;

    int m0 = blockIdx.y * BM;
    int n0 = blockIdx.x * BN;
    int tid  = threadIdx.x;
    int warp = tid >> 5;
    int wm0 = (warp % WRM) * TM;
    int wn0 = (warp / WRM) * TN;

    auto load_stage = [&](int s, int kt) {
        float* sAs = sA + s * AEL;
        float* sBs = sB + s * BEL;
        if (!AC) {
            constexpr int IT = (BM * (BK / 4)) / 256;
            #pragma unroll
            for (int t = 0; t < IT; t++) {
                int idx = t * 256 + tid;
                int r = idx >> 3, c = idx & 7;
                cpa16(sAs + r * LDAS + c * 4,
                      A + (long)(m0 + r) * lda + kt + c * 4);
            }
        } else {
            constexpr int PR = BM / 4;
            constexpr int IT = (BK * PR) / 256;
            #pragma unroll
            for (int t = 0; t < IT; t++) {
                int idx = t * 256 + tid;
                int k = idx / PR, mc = idx % PR;
                cpa16(sAs + k * LDAS + mc * 4,
                      A + (long)(kt + k) * lda + m0 + mc * 4);
            }
        }
        if (!BC) {
            constexpr int PR = BN / 4;
            constexpr int IT = (BK * PR) / 256;
            #pragma unroll
            for (int t = 0; t < IT; t++) {
                int idx = t * 256 + tid;
                int r = idx / PR, c = idx % PR;
                cpa16(sBs + r * LDBS + c * 4,
                      Bm + (long)(kt + r) * ldb + n0 + c * 4);
            }
        } else {
            constexpr int IT = (BN * (BK / 4)) / 256;
            #pragma unroll
            for (int t = 0; t < IT; t++) {
                int idx = t * 256 + tid;
                int n = idx >> 3, c = idx & 7;
                cpa16(sBs + n * LDBS + c * 4,
                      Bm + (long)(n0 + n) * ldb + kt + c * 4);
            }
        }
        asm volatile("cp.async.commit_group;\n");
    };

    using ALay = typename std::conditional<AC, wmma::col_major, wmma::row_major>::type;
    using BLay = typename std::conditional<BC, wmma::col_major, wmma::row_major>::type;

    wmma::fragment<wmma::accumulator, 16, 16, 8, float> fc[FM][FN];
    #pragma unroll
    for (int i = 0; i < FM; i++)
        #pragma unroll
        for (int j = 0; j < FN; j++)
            wmma::fill_fragment(fc[i][j], 0.f);

    int T = K / BK;
    load_stage(0, 0);
    if (T > 1) load_stage(1, BK);

    for (int kt = 0; kt < T; kt++) {
        if (kt + 1 < T) asm volatile("cp.async.wait_group 1;\n");
        else            asm volatile("cp.async.wait_group 0;\n");
        __syncthreads();
        if (kt + 2 < T) load_stage((kt + 2) % NST, (kt + 2) * BK);

        int s = kt % NST;
        const float* sAs = sA + s * AEL;
        const float* sBs = sB + s * BEL;

        #pragma unroll
        for (int kk = 0; kk < BK; kk += 8) {
            wmma::fragment<wmma::matrix_a, 16, 16, 8, wmma::precision::tf32, ALay> fa[FM];
            wmma::fragment<wmma::matrix_b, 16, 16, 8, wmma::precision::tf32, BLay> fb[FN];
            #pragma unroll
            for (int i = 0; i < FM; i++) {
                const float* ap = AC ? (sAs + kk * LDAS + wm0 + i * 16)
                                     : (sAs + (wm0 + i * 16) * LDAS + kk);
                wmma::load_matrix_sync(fa[i], ap, LDAS);
            }
            #pragma unroll
            for (int j = 0; j < FN; j++) {
                const float* bp = BC ? (sBs + (wn0 + j * 16) * LDBS + kk)
                                     : (sBs + kk * LDBS + wn0 + j * 16);
                wmma::load_matrix_sync(fb[j], bp, LDBS);
            }
            #pragma unroll
            for (int i = 0; i < FM; i++)
                #pragma unroll
                for (int j = 0; j < FN; j++)
                    wmma::mma_sync(fc[i][j], fa[i], fb[j], fc[i][j]);
        }
    }

    if (EPI == 0) {
        #pragma unroll
        for (int i = 0; i < FM; i++)
            #pragma unroll
            for (int j = 0; j < FN; j++) {
                #pragma unroll
                for (int t = 0; t < fc[i][j].num_elements; t++) {
                    float vv = fc[i][j].x[t] * alpha;
                    fc[i][j].x[t] = RND ? tf32r(vv) : vv;
                }
                wmma::store_matrix_sync(
                    C + (long)(m0 + wm0 + i * 16) * ldc + n0 + wn0 + j * 16,
                    fc[i][j], ldc, wmma::mem_row_major);
            }
    } else {
        __syncthreads();   // all warps done with pipeline smem before aliasing
        #pragma unroll
        for (int i = 0; i < FM; i++)
            #pragma unroll
            for (int j = 0; j < FN; j++)
                wmma::store_matrix_sync(sC + (wm0 + i * 16) * LDCS + wn0 + j * 16,
                                        fc[i][j], LDCS, wmma::mem_row_major);
        __syncthreads();
        constexpr int NB4 = BN / 4;
        for (int idx = tid; idx < BM * NB4; idx += 256) {
            int r = idx / NB4, c4 = (idx % NB4) * 4;
            int gm = m0 + r, gn = n0 + c4;
            float4 vv = *(const float4*)(sC + r * LDCS + c4);
            float4 bb = *(const float4*)(bias + gn);
            if (EPI == 2) {
                float4 rr = *(const float4*)(res + (long)gm * ldr + gn);
                vv.x += bb.x + rr.x; vv.y += bb.y + rr.y;
                vv.z += bb.z + rr.z; vv.w += bb.w + rr.w;
            } else {
                vv.x += bb.x; vv.y += bb.y; vv.z += bb.z; vv.w += bb.w;
                vv.x = 0.5f * vv.x * (1.f + erff(vv.x * 0.7071067811865476f));
                vv.y = 0.5f * vv.y * (1.f + erff(vv.y * 0.7071067811865476f));
                vv.z = 0.5f * vv.z * (1.f + erff(vv.z * 0.7071067811865476f));
                vv.w = 0.5f * vv.w * (1.f + erff(vv.w * 0.7071067811865476f));
                if (RND) {
                    vv.x = tf32r(vv.x); vv.y = tf32r(vv.y);
                    vv.z = tf32r(vv.z); vv.w = tf32r(vv.w);
                }
            }
            *(float4*)(C + (long)gm * ldc + gn) = vv;
        }
    }
}

// host-side smem size (mirrors kernel constexprs)
static constexpr size_t smemb(int BM, int BN, bool AC, bool BC, int EPI)
{
    int LDAS = AC ? BM + 4 : 36;
    int AEL  = AC ? 32 * LDAS : BM * LDAS;
    int LDBS = BC ? 36 : BN + 4;
    int BEL  = BC ? BN * LDBS : 32 * LDBS;
    int pipe = 3 * (AEL + BEL);
    int epi  = EPI ? BM * (BN + 4) : 0;
    return 4u * (size_t)(pipe > epi ? pipe : epi);
}

#define LAUNCH_GEMM(BM, BN, AC, BC, EPI, RND, grid, ...)                        \
    do {                                                                        \
        auto kfn = gemm2<BM, BN, AC, BC, EPI, RND>;                             \
        size_t smb = smemb(BM, BN, AC, BC, EPI);                                \
        cudaFuncSetAttribute(kfn, cudaFuncAttributeMaxDynamicSharedMemorySize,  \
                             (int)smb);                                         \
        kfn<<<grid, 256, smb>>>(__VA_ARGS__);                                   \
    } while (0)

// ---------------- host ----------------------------------------------------
extern "C" void kernel_launch(void* const* d_in, const int* in_sizes, int n_in,
                              void* d_out, int out_size)
{
    (void)in_sizes; (void)n_in; (void)out_size;
    const float* x      = (const float*)d_in[0];
    const float* ctx    = (const float*)d_in[1];
    const void*  mask   = d_in[2];
    const void*  cmask  = d_in[3];
    const float* ln_x_g = (const float*)d_in[4];
    const float* ln_x_b = (const float*)d_in[5];
    const float* ln_c_g = (const float*)d_in[6];
    const float* ln_c_b = (const float*)d_in[7];
    const float* W_qk   = (const float*)d_in[8];
    const float* W_v    = (const float*)d_in[9];
    const float* Wc_qk  = (const float*)d_in[10];
    const float* Wc_v   = (const float*)d_in[11];
    const float* W_out  = (const float*)d_in[12];
    const float* b_out  = (const float*)d_in[13];
    const float* Wc_out = (const float*)d_in[14];
    const float* bc_out = (const float*)d_in[15];
    const float* ff_g   = (const float*)d_in[16];
    const float* ff_b   = (const float*)d_in[17];
    const float* ff_w1  = (const float*)d_in[18];
    const float* ff_b1  = (const float*)d_in[19];
    const float* ff_w2  = (const float*)d_in[20];
    const float* ff_b2  = (const float*)d_in[21];
    const float* cff_g  = (const float*)d_in[22];
    const float* cff_b  = (const float*)d_in[23];
    const float* cff_w1 = (const float*)d_in[24];
    const float* cff_b1 = (const float*)d_in[25];
    const float* cff_w2 = (const float*)d_in[26];
    const float* cff_b2 = (const float*)d_in[27];
    float* outp = (float*)d_out;

    float *xn, *cn, *qk, *v, *cqk, *cv, *sim, *attn, *cattn, *out, *cout, *x1, *c1, *hbuf, *wr;
    cudaGetSymbolAddress((void**)&xn,    g_xn);
    cudaGetSymbolAddress((void**)&cn,    g_cn);
    cudaGetSymbolAddress((void**)&qk,    g_qk);
    cudaGetSymbolAddress((void**)&v,     g_v);
    cudaGetSymbolAddress((void**)&cqk,   g_cqk);
    cudaGetSymbolAddress((void**)&cv,    g_cv);
    cudaGetSymbolAddress((void**)&sim,   g_sim);
    cudaGetSymbolAddress((void**)&attn,  g_attn);
    cudaGetSymbolAddress((void**)&cattn, g_cattn);
    cudaGetSymbolAddress((void**)&out,   g_out);
    cudaGetSymbolAddress((void**)&cout,  g_cout);
    cudaGetSymbolAddress((void**)&x1,    g_x1);
    cudaGetSymbolAddress((void**)&c1,    g_c1);
    cudaGetSymbolAddress((void**)&hbuf,  g_h);
    cudaGetSymbolAddress((void**)&wr,    g_wr);

    const float SCALE = 0.125f;   // DH^-0.5 = 64^-0.5

    // 0) detect mask dtype; round all weights to tf32 once
    detect_mask_mode<<<1, 256>>>((const float*)mask, (Bb * Nn) / 4);
    #define RW(src, off, n) \
        tf32_round_k<<<512, 256>>>((const float4*)(src), (float4*)(wr + (off)), (n) / 4)
    RW(W_qk,   OFF_WQK,   Dd * INNERi);
    RW(W_v,    OFF_WV,    Dd * INNERi);
    RW(Wc_qk,  OFF_WCQK,  Dd * INNERi);
    RW(Wc_v,   OFF_WCV,   Dd * INNERi);
    RW(W_out,  OFF_WOUT,  INNERi * Dd);
    RW(Wc_out, OFF_WCOUT, INNERi * Dd);
    RW(ff_w1,  OFF_FFW1,  Dd * FFDf);
    RW(ff_w2,  OFF_FFW2,  FFDf * Dd);
    RW(cff_w1, OFF_CFFW1, Dd * FFDf);
    RW(cff_w2, OFF_CFFW2, FFDf * Dd);
    #undef RW

    // 1) pre-norm (outputs tf32-rounded)
    ln_k<<<Bb * Nn,  256>>>(x,   ln_x_g, ln_x_b, xn, Dd);
    ln_k<<<Bb * MM_, 256>>>(ctx, ln_c_g, ln_c_b, cn, Dd);

    // 2) projections (outputs tf32-rounded)
    LAUNCH_GEMM(64, 128, false, false, 0, true,
                dim3(INNERi / 128, Bb * Nn / 64, 1),
                xn, Dd, 0, 0, wr + OFF_WQK, INNERi, 0, 0, qk, INNERi, 0, 0,
                nullptr, nullptr, 0, Dd, 1.f, 1);
    LAUNCH_GEMM(64, 128, false, false, 0, true,
                dim3(INNERi / 128, Bb * Nn / 64, 1),
                xn, Dd, 0, 0, wr + OFF_WV, INNERi, 0, 0, v, INNERi, 0, 0,
                nullptr, nullptr, 0, Dd, 1.f, 1);
    LAUNCH_GEMM(64, 128, false, false, 0, true,
                dim3(INNERi / 128, Bb * MM_ / 64, 1),
                cn, Dd, 0, 0, wr + OFF_WCQK, INNERi, 0, 0, cqk, INNERi, 0, 0,
                nullptr, nullptr, 0, Dd, 1.f, 1);
    LAUNCH_GEMM(64, 128, false, false, 0, true,
                dim3(INNERi / 128, Bb * MM_ / 64, 1),
                cn, Dd, 0, 0, wr + OFF_WCV, INNERi, 0, 0, cv, INNERi, 0, 0,
                nullptr, nullptr, 0, Dd, 1.f, 1);

    // 3) sim[b,h] = qk[b,:,h,:] @ cqk[b,:,h,:]^T * SCALE  (plain f32 output)
    LAUNCH_GEMM(128, 128, false, true, 0, false,
                dim3(MM_ / 128, Nn / 128, Bb * Hh),
                qk,  INNERi, (long)Nn  * INNERi, DHd,
                cqk, INNERi, (long)MM_ * INNERi, DHd,
                sim, MM_,    (long)Hh * Nn * MM_, (long)Nn * MM_,
                nullptr, nullptr, 0, DHd, SCALE, Hh);

    // 4) dual softmax (outputs tf32-rounded)
    softmax_row<<<Bb * Hh * Nn, 256>>>(sim, attn, mask, cmask);
    softmax_col<<<dim3(MM_ / 32, Bb * Hh), 256>>>(sim, cattn, mask, cmask);

    // 5) out = attn @ cv ;  cout = cattn^T @ v  (outputs tf32-rounded)
    LAUNCH_GEMM(128, 64, false, false, 0, true,
                dim3(1, Nn / 128, Bb * Hh),
                attn, MM_,   (long)Hh * Nn * MM_, (long)Nn * MM_,
                cv,  INNERi, (long)MM_ * INNERi, DHd,
                out, INNERi, (long)Nn  * INNERi, DHd,
                nullptr, nullptr, 0, MM_, 1.f, Hh);
    LAUNCH_GEMM(128, 64, true, false, 0, true,
                dim3(1, MM_ / 128, Bb * Hh),
                cattn, MM_,  (long)Hh * Nn * MM_, (long)Nn * MM_,
                v,   INNERi, (long)Nn  * INNERi, DHd,
                cout, INNERi, (long)MM_ * INNERi, DHd,
                nullptr, nullptr, 0, Nn, 1.f, Hh);

    // 6) output projection + residual (full f32 output)
    LAUNCH_GEMM(128, 128, false, false, 2, false,
                dim3(Dd / 128, Bb * Nn / 128, 1),
                out, INNERi, 0, 0, wr + OFF_WOUT, Dd, 0, 0, x1, Dd, 0, 0,
                b_out, x, Dd, INNERi, 1.f, 1);
    LAUNCH_GEMM(128, 128, false, false, 2, false,
                dim3(Dd / 128, Bb * MM_ / 128, 1),
                cout, INNERi, 0, 0, wr + OFF_WCOUT, Dd, 0, 0, c1, Dd, 0, 0,
                bc_out, ctx, Dd, INNERi, 1.f, 1);

    // 7) FFN (x side) -> d_out[0 : B*N*D)
    ln_k<<<Bb * Nn, 256>>>(x1, ff_g, ff_b, xn, Dd);
    LAUNCH_GEMM(128, 128, false, false, 3, true,
                dim3(FFDf / 128, Bb * Nn / 128, 1),
                xn, Dd, 0, 0, wr + OFF_FFW1, FFDf, 0, 0, hbuf, FFDf, 0, 0,
                ff_b1, nullptr, 0, Dd, 1.f, 1);
    LAUNCH_GEMM(128, 128, false, false, 2, false,
                dim3(Dd / 128, Bb * Nn / 128, 1),
                hbuf, FFDf, 0, 0, wr + OFF_FFW2, Dd, 0, 0, outp, Dd, 0, 0,
                ff_b2, x1, Dd, FFDf, 1.f, 1);

    // 8) FFN (context side) -> d_out[B*N*D : 2*B*N*D)
    ln_k<<<Bb * MM_, 256>>>(c1, cff_g, cff_b, cn, Dd);
    LAUNCH_GEMM(128, 128, false, false, 3, true,
                dim3(FFDf / 128, Bb * MM_ / 128, 1),
                cn, Dd, 0, 0, wr + OFF_CFFW1, FFDf, 0, 0, hbuf, FFDf, 0, 0,
                cff_b1, nullptr, 0, Dd, 1.f, 1);
    LAUNCH_GEMM(128, 128, false, false, 2, false,
                dim3(Dd / 128, Bb * MM_ / 128, 1),
                hbuf, FFDf, 0, 0, wr + OFF_CFFW2, Dd, 0, 0, outp + (long)Bb * Nn * Dd, Dd, 0, 0,
                cff_b2, c1, Dd, FFDf, 1.f, 1);
}